// round 3
// baseline (speedup 1.0000x reference)
#include <cuda_runtime.h>
#include <cstdint>

// EdgeConv: B=16, N=8192, K=20, D=64
// y[p][o] = x[p]·W1[o],  z[p][o] = x[p]·(W2[o]-W1[o])
// out = gelu(LN(z[p] + max_k y[ind[p][k]]))

#define B_  16
#define N_  8192
#define K_  20
#define P_  (B_ * N_)   // 131072 points

__device__ float g_y[(size_t)P_ * 64];   // 33.5 MB
__device__ float g_z[(size_t)P_ * 64];   // 33.5 MB

#define FMA2(d, a, b, c) \
    asm("fma.rn.f32x2 %0, %1, %2, %3;" : "=l"(d) : "l"(a), "l"(b), "l"(c))

__device__ __forceinline__ unsigned lo32(unsigned long long v) { return (unsigned)v; }
__device__ __forceinline__ unsigned hi32(unsigned long long v) { return (unsigned)(v >> 32); }

// ---------------------------------------------------------------------------
// Kernel 1: block tile = 64 points x 128 outputs, 256 threads, 2048 blocks.
// Thread tile = 2 points x 16 outputs  ->  acc = 16 u64 = 32 regs (no spills).
// og = tid&7 owns logical outputs [og*16, og*16+16); pg = tid>>3 owns 2 pts.
// W in smem, chunk-permuted: logical o = og*16 + j*4 + e at phys
// d*128 + j*32 + og*4 + e  ->  each warp LDS.128 covers 128B contiguous,
// 4x broadcast, conflict-free.
// ---------------------------------------------------------------------------
__global__ __launch_bounds__(256, 3)
void k1_gemm(const float* __restrict__ x, const float* __restrict__ W)
{
    __shared__ float Wsm[64 * 128];   // 32 KB

    for (int i = threadIdx.x; i < 64 * 128; i += 256) {
        int d = i >> 7, o = i & 127;
        float v;
        if (o < 64) v = W[o * 128 + d];
        else        v = W[(o - 64) * 128 + 64 + d] - W[(o - 64) * 128 + d];
        int phys = d * 128 + ((o >> 2) & 3) * 32 + (o >> 4) * 4 + (o & 3);
        Wsm[phys] = v;
    }
    __syncthreads();

    const int og = threadIdx.x & 7;
    const int pg = threadIdx.x >> 3;            // 0..31, 2 points each
    const size_t p0 = (size_t)blockIdx.x * 64 + (size_t)pg * 2;

    // acc[pt*8 + q] : f32x2 pair, outputs (og*16 + q*2, +1) logical-permuted
    unsigned long long acc[16];
#pragma unroll
    for (int q = 0; q < 16; q++) acc[q] = 0ull;

    const float4* xb = (const float4*)(x + p0 * 64);   // pt0: [0..16), pt1: [16..32)

#pragma unroll 2
    for (int d4 = 0; d4 < 16; d4++) {
        float4 xa0 = __ldg(xb + d4);
        float4 xa1 = __ldg(xb + 16 + d4);
#pragma unroll
        for (int dd = 0; dd < 4; dd++) {
            const float* wr = Wsm + (d4 * 4 + dd) * 128 + og * 4;
            uint4 w0 = *(const uint4*)(wr);
            uint4 w1 = *(const uint4*)(wr + 32);
            uint4 w2 = *(const uint4*)(wr + 64);
            uint4 w3 = *(const uint4*)(wr + 96);
            unsigned long long wj[8];
            wj[0] = (unsigned long long)w0.x | ((unsigned long long)w0.y << 32);
            wj[1] = (unsigned long long)w0.z | ((unsigned long long)w0.w << 32);
            wj[2] = (unsigned long long)w1.x | ((unsigned long long)w1.y << 32);
            wj[3] = (unsigned long long)w1.z | ((unsigned long long)w1.w << 32);
            wj[4] = (unsigned long long)w2.x | ((unsigned long long)w2.y << 32);
            wj[5] = (unsigned long long)w2.z | ((unsigned long long)w2.w << 32);
            wj[6] = (unsigned long long)w3.x | ((unsigned long long)w3.y << 32);
            wj[7] = (unsigned long long)w3.z | ((unsigned long long)w3.w << 32);

            unsigned long long pa0, pa1;
            asm("mov.b64 %0, {%1, %1};" : "=l"(pa0) : "r"(__float_as_uint((&xa0.x)[dd])));
            asm("mov.b64 %0, {%1, %1};" : "=l"(pa1) : "r"(__float_as_uint((&xa1.x)[dd])));
#pragma unroll
            for (int q = 0; q < 8; q++) {
                FMA2(acc[q],     pa0, wj[q], acc[q]);
                FMA2(acc[8 + q], pa1, wj[q], acc[8 + q]);
            }
        }
    }

    // og 0..3 -> y (obase og*16), og 4..7 -> z (obase (og-4)*16)
    float* base = (og < 4) ? (g_y + p0 * 64 + og * 16)
                           : (g_z + p0 * 64 + (og - 4) * 16);
#pragma unroll
    for (int pt = 0; pt < 2; pt++) {
        float4* dst = (float4*)(base + pt * 64);
#pragma unroll
        for (int j = 0; j < 4; j++) {
            unsigned long long a0 = acc[pt * 8 + j * 2];
            unsigned long long a1 = acc[pt * 8 + j * 2 + 1];
            float4 v;
            v.x = __uint_as_float(lo32(a0));
            v.y = __uint_as_float(hi32(a0));
            v.z = __uint_as_float(lo32(a1));
            v.w = __uint_as_float(hi32(a1));
            dst[j] = v;
        }
    }
}

// ---------------------------------------------------------------------------
// Kernel 2: warp per point, lane owns dims (2*lane, 2*lane+1).
// Indices via 20 uniform __ldg loads (warp-broadcast, 1 sector) - no SHFL.
// ---------------------------------------------------------------------------
__global__ __launch_bounds__(256)
void k2_gather(const int*   __restrict__ ind,
               const float* __restrict__ gamma,
               const float* __restrict__ beta,
               float*       __restrict__ out)
{
    int warp = threadIdx.x >> 5, lane = threadIdx.x & 31;
    size_t p = (size_t)blockIdx.x * 8 + warp;
    size_t bbase = (p >> 13) << 13;   // b * N

    const int*  ip    = ind + p * K_;
    const char* ybase = (const char*)(g_y + (bbase << 6)) + lane * 8;

    float m0 = -3.402823466e+38f, m1 = -3.402823466e+38f;
#pragma unroll
    for (int k = 0; k < K_; k++) {
        int j = __ldg(ip + k);
        float2 yv = *(const float2*)(ybase + ((size_t)j << 8));
        m0 = fmaxf(m0, yv.x);
        m1 = fmaxf(m1, yv.y);
    }

    float2 zv = *(const float2*)(g_z + (p << 6) + lane * 2);
    float h0 = m0 + zv.x, h1 = m1 + zv.y;

    float s  = h0 + h1;
    float ss = h0 * h0 + h1 * h1;
#pragma unroll
    for (int o2 = 16; o2; o2 >>= 1) {
        s  += __shfl_xor_sync(0xffffffffu, s, o2);
        ss += __shfl_xor_sync(0xffffffffu, ss, o2);
    }
    float mu  = s * (1.0f / 64.0f);
    float var = fmaxf(ss * (1.0f / 64.0f) - mu * mu, 0.0f);
    float rs  = rsqrtf(var + 1e-5f);

    float2 g  = *(const float2*)(gamma + lane * 2);
    float2 be = *(const float2*)(beta  + lane * 2);
    float hn0 = (h0 - mu) * rs * g.x + be.x;
    float hn1 = (h1 - mu) * rs * g.y + be.y;

    float r0 = 0.5f * hn0 * (1.0f + erff(hn0 * 0.7071067811865475f));
    float r1 = 0.5f * hn1 * (1.0f + erff(hn1 * 0.7071067811865475f));

    *(float2*)(out + (p << 6) + lane * 2) = make_float2(r0, r1);
}

// ---------------------------------------------------------------------------
extern "C" void kernel_launch(void* const* d_in, const int* in_sizes, int n_in,
                              void* d_out, int out_size)
{
    const float* x     = (const float*)d_in[0];
    const int*   ind   = (const int*)  d_in[1];
    const float* W     = (const float*)d_in[2];
    const float* gamma = (const float*)d_in[3];
    const float* beta  = (const float*)d_in[4];
    float*       out   = (float*)d_out;

    k1_gemm  <<<P_ / 64, 256>>>(x, W);
    k2_gather<<<P_ / 8,  256>>>(ind, gamma, beta, out);
}

// round 4
// speedup vs baseline: 1.4403x; 1.4403x over previous
#include <cuda_runtime.h>
#include <cstdint>

// EdgeConv: B=16, N=8192, K=20, D=64
// y[p][o] = x[p]·W1[o],  z[p][o] = x[p]·(W2[o]-W1[o])
// out = gelu(LN(z[p] + max_k y[ind[p][k]]))

#define B_  16
#define N_  8192
#define K_  20
#define P_  (B_ * N_)   // 131072 points

__device__ float g_y[(size_t)P_ * 64];   // 33.5 MB
__device__ float g_z[(size_t)P_ * 64];   // 33.5 MB

#define FMA2(d, a, b, c) \
    asm("fma.rn.f32x2 %0, %1, %2, %3;" : "=l"(d) : "l"(a), "l"(b), "l"(c))

// Dummy: shifts ncu's -s 5 -c 1 capture window onto k1 (launch #5 = k1).
__global__ void k0_dummy() {}

// ---------------------------------------------------------------------------
// Kernel 1: block tile = 128 points x 128 outputs, 256 threads, 1024 blocks.
// Thread tile = 4 points x 16 outputs. acc = 32 u64. W reused 4x per LDS.
// og = tid&7 owns logical outputs [og*16, og*16+16); pg = tid>>3 owns 4 pts.
// W in smem, chunk-permuted: logical o = og*16 + j*4 + e at phys float index
// d*128 + j*32 + og*4 + e  ->  warp's 8 distinct LDS.128 span 128B contiguous
// (broadcast x4), conflict-free. Read directly as ulonglong2: LDS.128 dest
// regs are already the aligned pairs fma.rn.f32x2 needs (no repacking MOVs).
// ---------------------------------------------------------------------------
__global__ __launch_bounds__(256, 2)
void k1_gemm(const float* __restrict__ x, const float* __restrict__ W)
{
    __shared__ __align__(16) float Wsm[64 * 128];   // 32 KB

    for (int i = threadIdx.x; i < 64 * 128; i += 256) {
        int d = i >> 7, o = i & 127;
        float v;
        if (o < 64) v = W[o * 128 + d];
        else        v = W[(o - 64) * 128 + 64 + d] - W[(o - 64) * 128 + d];
        int phys = d * 128 + ((o >> 2) & 3) * 32 + (o >> 4) * 4 + (o & 3);
        Wsm[phys] = v;
    }
    __syncthreads();

    const int og = threadIdx.x & 7;     // output group
    const int pg = threadIdx.x >> 3;    // point group: 4 points
    const size_t p0 = (size_t)blockIdx.x * 128 + (size_t)pg * 4;

    // acc[pt*8 + q]: f32x2 pair for outputs (og*16 + q*2, +1) [permuted order]
    unsigned long long acc[32];
#pragma unroll
    for (int q = 0; q < 32; q++) acc[q] = 0ull;

    const float4* xb = (const float4*)(x + p0 * 64);   // 16 float4 per point

#pragma unroll 2
    for (int d4 = 0; d4 < 16; d4++) {
        float4 xc0 = __ldg(xb + d4);
        float4 xc1 = __ldg(xb + 16 + d4);
        float4 xc2 = __ldg(xb + 32 + d4);
        float4 xc3 = __ldg(xb + 48 + d4);
#pragma unroll
        for (int dd = 0; dd < 4; dd++) {
            const ulonglong2* wr =
                (const ulonglong2*)(Wsm + (d4 * 4 + dd) * 128 + og * 4);
            ulonglong2 wA = wr[0];    // q0,q1   (+0   floats)
            ulonglong2 wB = wr[8];    // q2,q3   (+32  floats)
            ulonglong2 wC = wr[16];   // q4,q5   (+64  floats)
            ulonglong2 wD = wr[24];   // q6,q7   (+96  floats)

            float xs[4] = { (&xc0.x)[dd], (&xc1.x)[dd], (&xc2.x)[dd], (&xc3.x)[dd] };
#pragma unroll
            for (int pt = 0; pt < 4; pt++) {
                unsigned long long pa;
                asm("mov.b64 %0, {%1, %1};" : "=l"(pa) : "r"(__float_as_uint(xs[pt])));
                FMA2(acc[pt * 8 + 0], pa, wA.x, acc[pt * 8 + 0]);
                FMA2(acc[pt * 8 + 1], pa, wA.y, acc[pt * 8 + 1]);
                FMA2(acc[pt * 8 + 2], pa, wB.x, acc[pt * 8 + 2]);
                FMA2(acc[pt * 8 + 3], pa, wB.y, acc[pt * 8 + 3]);
                FMA2(acc[pt * 8 + 4], pa, wC.x, acc[pt * 8 + 4]);
                FMA2(acc[pt * 8 + 5], pa, wC.y, acc[pt * 8 + 5]);
                FMA2(acc[pt * 8 + 6], pa, wD.x, acc[pt * 8 + 6]);
                FMA2(acc[pt * 8 + 7], pa, wD.y, acc[pt * 8 + 7]);
            }
        }
    }

    // og 0..3 -> y (obase og*16), og 4..7 -> z (obase (og-4)*16)
    float* base = (og < 4) ? (g_y + p0 * 64 + og * 16)
                           : (g_z + p0 * 64 + (og - 4) * 16);
#pragma unroll
    for (int pt = 0; pt < 4; pt++) {
        ulonglong2* dst = (ulonglong2*)(base + pt * 64);
#pragma unroll
        for (int j = 0; j < 4; j++)
            dst[j] = make_ulonglong2(acc[pt * 8 + j * 2], acc[pt * 8 + j * 2 + 1]);
    }
}

// ---------------------------------------------------------------------------
// Kernel 2: warp per point, lane owns dims (2*lane, 2*lane+1).
// Indices via 20 uniform __ldg loads (warp-broadcast) - no SHFL chain.
// ---------------------------------------------------------------------------
__global__ __launch_bounds__(256)
void k2_gather(const int*   __restrict__ ind,
               const float* __restrict__ gamma,
               const float* __restrict__ beta,
               float*       __restrict__ out)
{
    int warp = threadIdx.x >> 5, lane = threadIdx.x & 31;
    size_t p = (size_t)blockIdx.x * 8 + warp;
    size_t bbase = (p >> 13) << 13;   // b * N

    const int*  ip    = ind + p * K_;
    const char* ybase = (const char*)(g_y + (bbase << 6)) + lane * 8;

    float m0 = -3.402823466e+38f, m1 = -3.402823466e+38f;
#pragma unroll
    for (int k = 0; k < K_; k++) {
        int j = __ldg(ip + k);
        float2 yv = *(const float2*)(ybase + ((size_t)j << 8));
        m0 = fmaxf(m0, yv.x);
        m1 = fmaxf(m1, yv.y);
    }

    float2 zv = *(const float2*)(g_z + (p << 6) + lane * 2);
    float h0 = m0 + zv.x, h1 = m1 + zv.y;

    float s  = h0 + h1;
    float ss = h0 * h0 + h1 * h1;
#pragma unroll
    for (int o2 = 16; o2; o2 >>= 1) {
        s  += __shfl_xor_sync(0xffffffffu, s, o2);
        ss += __shfl_xor_sync(0xffffffffu, ss, o2);
    }
    float mu  = s * (1.0f / 64.0f);
    float var = fmaxf(ss * (1.0f / 64.0f) - mu * mu, 0.0f);
    float rs  = rsqrtf(var + 1e-5f);

    float2 g  = *(const float2*)(gamma + lane * 2);
    float2 be = *(const float2*)(beta  + lane * 2);
    float hn0 = (h0 - mu) * rs * g.x + be.x;
    float hn1 = (h1 - mu) * rs * g.y + be.y;

    float r0 = 0.5f * hn0 * (1.0f + erff(hn0 * 0.7071067811865475f));
    float r1 = 0.5f * hn1 * (1.0f + erff(hn1 * 0.7071067811865475f));

    *(float2*)(out + (p << 6) + lane * 2) = make_float2(r0, r1);
}

// ---------------------------------------------------------------------------
extern "C" void kernel_launch(void* const* d_in, const int* in_sizes, int n_in,
                              void* d_out, int out_size)
{
    const float* x     = (const float*)d_in[0];
    const int*   ind   = (const int*)  d_in[1];
    const float* W     = (const float*)d_in[2];
    const float* gamma = (const float*)d_in[3];
    const float* beta  = (const float*)d_in[4];
    float*       out   = (float*)d_out;

    // 4 launches/call => ncu (-s 5 -c 1) captures launch #5 = k1 on call 2.
    k0_dummy <<<1, 32>>>();
    k1_gemm  <<<P_ / 128, 256>>>(x, W);
    k2_gather<<<P_ / 8,   256>>>(ind, gamma, beta, out);
    k0_dummy <<<1, 32>>>();
}

// round 6
// speedup vs baseline: 2.6019x; 1.8065x over previous
#include <cuda_runtime.h>
#include <cuda_bf16.h>
#include <cstdint>

// EdgeConv: B=16, N=8192, K=20, D=64
// Wc[o][d] = W[o][d] (o<64) ; W[o-64][64+d]-W[o-64][d] (o>=64)
// y[p][o]=x[p]·Wc[o] (o<64), z via o>=64.  out = gelu(LN(z + max_k y[ind]))
// k1 via mma.sync bf16 3-split: x=xh+xl, Wc=Wh+Wl; y = xh*Wh + xh*Wl + xl*Wh.

#define B_  16
#define N_  8192
#define K_  20
#define P_  (B_ * N_)   // 131072

__device__ float g_y[(size_t)P_ * 64];
__device__ float g_z[(size_t)P_ * 64];
__device__ unsigned short g_Wh[128 * 64];   // bf16 Wc hi, row o, 128B rows
__device__ unsigned short g_Wl[128 * 64];   // bf16 Wc lo

__device__ __forceinline__ uint32_t smem_u32(const void* p) {
    uint32_t a;
    asm("{ .reg .u64 t; cvta.to.shared.u64 t, %1; cvt.u32.u64 %0, t; }"
        : "=r"(a) : "l"(p));
    return a;
}
#define SWZ(x) ((x) ^ (((x) >> 3) & 0x70))

#define LDSM_X4(r, a) \
    asm volatile("ldmatrix.sync.aligned.m8n8.x4.shared.b16 {%0,%1,%2,%3}, [%4];" \
        : "=r"((r)[0]), "=r"((r)[1]), "=r"((r)[2]), "=r"((r)[3]) : "r"(a))
#define LDSM_X2(r, a) \
    asm volatile("ldmatrix.sync.aligned.m8n8.x2.shared.b16 {%0,%1}, [%2];" \
        : "=r"((r)[0]), "=r"((r)[1]) : "r"(a))
#define MMA_BF16(c, a, b) \
    asm volatile("mma.sync.aligned.m16n8k16.row.col.f32.bf16.bf16.f32 " \
        "{%0,%1,%2,%3}, {%4,%5,%6,%7}, {%8,%9}, {%0,%1,%2,%3};" \
        : "+f"((c)[0]), "+f"((c)[1]), "+f"((c)[2]), "+f"((c)[3]) \
        : "r"((a)[0]), "r"((a)[1]), "r"((a)[2]), "r"((a)[3]), \
          "r"((b)[0]), "r"((b)[1]))

// dynamic smem regions (all 1024-aligned relative to base)
#define SM_AH 0
#define SM_AL 16384
#define SM_BH 32768
#define SM_BL 49152
#define SM_TOTAL 65536

__global__ void k0_dummy() {}

// ---------------------------------------------------------------------------
// prep: Wc -> bf16 hi/lo split, layout [o][d], 128 rows x 64 cols
// ---------------------------------------------------------------------------
__global__ void k_prep(const float* __restrict__ W)
{
    int idx = blockIdx.x * 256 + threadIdx.x;   // 0..8191
    int o = idx >> 6, d = idx & 63;
    float wc = (o < 64) ? W[o * 128 + d]
                        : W[(o - 64) * 128 + 64 + d] - W[(o - 64) * 128 + d];
    __nv_bfloat16 h = __float2bfloat16(wc);
    __nv_bfloat16 l = __float2bfloat16(wc - __bfloat162float(h));
    g_Wh[idx] = *(unsigned short*)&h;
    g_Wl[idx] = *(unsigned short*)&l;
}

// ---------------------------------------------------------------------------
// k1: CTA tile 128 pts x 128 outs, K=64. 8 warps, warp = 16 pts x 128 outs.
// HMMA m16n8k16 bf16, 3 split-products, fp32 accum.
// ---------------------------------------------------------------------------
__global__ __launch_bounds__(256, 2)
void k1_hmma(const float* __restrict__ x)
{
    extern __shared__ char smem[];
    const uint32_t sb = smem_u32(smem);
    const int tid = threadIdx.x, wid = tid >> 5, lane = tid & 31;
    const size_t p0 = (size_t)blockIdx.x * 128;

    // --- stage B (Wh/Wl), 128x64 bf16 each, SW128-swizzled 128B rows ---
#pragma unroll
    for (int i = 0; i < 4; i++) {
        int idx = i * 256 + tid;                     // uint4 units, 0..1023
        uint32_t off = SWZ((uint32_t)(idx * 16));
        *(uint4*)(smem + SM_BH + off) = ((const uint4*)g_Wh)[idx];
        *(uint4*)(smem + SM_BL + off) = ((const uint4*)g_Wl)[idx];
    }

    // --- stage A: x tile 128x64 f32 -> bf16 hi/lo, swizzled 8B stores ---
    const float4* xb = (const float4*)(x + p0 * 64);
#pragma unroll
    for (int i = 0; i < 8; i++) {
        int idx = i * 256 + tid;                     // float4 units, 0..2047
        int row = idx >> 4, c4 = idx & 15;
        float4 v = __ldg(xb + idx);
        float f[4] = { v.x, v.y, v.z, v.w };
        unsigned long long hv = 0ull, lv = 0ull;
#pragma unroll
        for (int e = 0; e < 4; e++) {
            __nv_bfloat16 h = __float2bfloat16(f[e]);
            __nv_bfloat16 l = __float2bfloat16(f[e] - __bfloat162float(h));
            hv |= (unsigned long long)(*(unsigned short*)&h) << (16 * e);
            lv |= (unsigned long long)(*(unsigned short*)&l) << (16 * e);
        }
        uint32_t off = SWZ((uint32_t)(row * 128 + c4 * 8));
        *(unsigned long long*)(smem + SM_AH + off) = hv;
        *(unsigned long long*)(smem + SM_AL + off) = lv;
    }
    __syncthreads();

    // --- A fragments for this warp: rows wid*16..+15, 4 k-tiles ---
    uint32_t ah[4][4], al[4][4];
    {
        int r  = wid * 16 + (lane & 15);
        int cb = (lane >> 4) * 16;                  // k byte offset 0 / 16
#pragma unroll
        for (int kt = 0; kt < 4; kt++) {
            uint32_t off = SWZ((uint32_t)(r * 128 + kt * 32 + cb));
            LDSM_X4(ah[kt], sb + SM_AH + off);
            LDSM_X4(al[kt], sb + SM_AL + off);
        }
    }

    // --- B-address lane component ---
    const int brow = lane & 7;
    const int bkb  = ((lane >> 3) & 1) * 16;        // k byte offset 0 / 16

    // --- loop over n-tiles in pairs (2-way acc ILP) ---
#pragma unroll
    for (int np = 0; np < 8; np++) {
        int nt0 = np * 2, nt1 = np * 2 + 1;
        uint32_t bh0[4][2], bl0[4][2], bh1[4][2], bl1[4][2];
#pragma unroll
        for (int kt = 0; kt < 4; kt++) {
            uint32_t o0 = SWZ((uint32_t)((nt0 * 8 + brow) * 128 + kt * 32 + bkb));
            uint32_t o1 = SWZ((uint32_t)((nt1 * 8 + brow) * 128 + kt * 32 + bkb));
            LDSM_X2(bh0[kt], sb + SM_BH + o0);
            LDSM_X2(bl0[kt], sb + SM_BL + o0);
            LDSM_X2(bh1[kt], sb + SM_BH + o1);
            LDSM_X2(bl1[kt], sb + SM_BL + o1);
        }
        float c0[4] = {0.f, 0.f, 0.f, 0.f};
        float c1[4] = {0.f, 0.f, 0.f, 0.f};
#pragma unroll
        for (int kt = 0; kt < 4; kt++) {
            MMA_BF16(c0, ah[kt], bh0[kt]);
            MMA_BF16(c1, ah[kt], bh1[kt]);
            MMA_BF16(c0, ah[kt], bl0[kt]);
            MMA_BF16(c1, ah[kt], bl1[kt]);
            MMA_BF16(c0, al[kt], bh0[kt]);
            MMA_BF16(c1, al[kt], bh1[kt]);
        }
        // --- store: nt<8 -> y, else z (col-64). C frag: lane t ->
        // (row t/4, col (t&3)*2) & (row t/4+8, same col), pairs contiguous.
        size_t row = p0 + (size_t)wid * 16 + (lane >> 2);
        {
            float* gb = (nt0 < 8) ? g_y : g_z;
            int col = (nt0 & 7) * 8 + (lane & 3) * 2;
            *(float2*)(gb + row * 64 + col)       = make_float2(c0[0], c0[1]);
            *(float2*)(gb + (row + 8) * 64 + col) = make_float2(c0[2], c0[3]);
        }
        {
            float* gb = (nt1 < 8) ? g_y : g_z;
            int col = (nt1 & 7) * 8 + (lane & 3) * 2;
            *(float2*)(gb + row * 64 + col)       = make_float2(c1[0], c1[1]);
            *(float2*)(gb + (row + 8) * 64 + col) = make_float2(c1[2], c1[3]);
        }
    }
}

// ---------------------------------------------------------------------------
// Kernel 2: warp per point, lane owns dims (2*lane, 2*lane+1).
// ---------------------------------------------------------------------------
__global__ __launch_bounds__(256)
void k2_gather(const int*   __restrict__ ind,
               const float* __restrict__ gamma,
               const float* __restrict__ beta,
               float*       __restrict__ out)
{
    int warp = threadIdx.x >> 5, lane = threadIdx.x & 31;
    size_t p = (size_t)blockIdx.x * 8 + warp;
    size_t bbase = (p >> 13) << 13;

    const int*  ip    = ind + p * K_;
    const char* ybase = (const char*)(g_y + (bbase << 6)) + lane * 8;

    float m0 = -3.402823466e+38f, m1 = -3.402823466e+38f;
#pragma unroll
    for (int k = 0; k < K_; k++) {
        int j = __ldg(ip + k);
        float2 yv = *(const float2*)(ybase + ((size_t)j << 8));
        m0 = fmaxf(m0, yv.x);
        m1 = fmaxf(m1, yv.y);
    }

    float2 zv = *(const float2*)(g_z + (p << 6) + lane * 2);
    float h0 = m0 + zv.x, h1 = m1 + zv.y;

    float s  = h0 + h1;
    float ss = h0 * h0 + h1 * h1;
#pragma unroll
    for (int o2 = 16; o2; o2 >>= 1) {
        s  += __shfl_xor_sync(0xffffffffu, s, o2);
        ss += __shfl_xor_sync(0xffffffffu, ss, o2);
    }
    float mu  = s * (1.0f / 64.0f);
    float var = fmaxf(ss * (1.0f / 64.0f) - mu * mu, 0.0f);
    float rs  = rsqrtf(var + 1e-5f);

    float2 g  = *(const float2*)(gamma + lane * 2);
    float2 be = *(const float2*)(beta  + lane * 2);
    float hn0 = (h0 - mu) * rs * g.x + be.x;
    float hn1 = (h1 - mu) * rs * g.y + be.y;

    float r0 = 0.5f * hn0 * (1.0f + erff(hn0 * 0.7071067811865475f));
    float r1 = 0.5f * hn1 * (1.0f + erff(hn1 * 0.7071067811865475f));

    *(float2*)(out + (p << 6) + lane * 2) = make_float2(r0, r1);
}

// ---------------------------------------------------------------------------
extern "C" void kernel_launch(void* const* d_in, const int* in_sizes, int n_in,
                              void* d_out, int out_size)
{
    const float* x     = (const float*)d_in[0];
    const int*   ind   = (const int*)  d_in[1];
    const float* W     = (const float*)d_in[2];
    const float* gamma = (const float*)d_in[3];
    const float* beta  = (const float*)d_in[4];
    float*       out   = (float*)d_out;

    cudaFuncSetAttribute(k1_hmma, cudaFuncAttributeMaxDynamicSharedMemorySize, SM_TOTAL);

    // ncu captures process-launch #4 -> k1_hmma.
    k_prep  <<<32, 256>>>(W);
    k0_dummy<<<1, 32>>>();
    k0_dummy<<<1, 32>>>();
    k1_hmma <<<P_ / 128, 256, SM_TOTAL>>>(x);
    k2_gather<<<P_ / 8, 256>>>(ind, gamma, beta, out);
}

// round 7
// speedup vs baseline: 2.6636x; 1.0237x over previous
#include <cuda_runtime.h>
#include <cuda_bf16.h>
#include <cstdint>

// EdgeConv: B=16, N=8192, K=20, D=64
// Wc[o][d] = W[o][d] (o<64) ; W[o-64][64+d]-W[o-64][d] (o>=64)
// y[p][o]=x[p]·Wc[o] (o<64), z via o>=64.  out = gelu(LN(z + max_k y[ind]))
// k1 via mma.sync bf16 3-split: x=xh+xl, Wc=Wh+Wl; y ~= xh*Wh + xh*Wl + xl*Wh.

#define B_  16
#define N_  8192
#define K_  20
#define P_  (B_ * N_)   // 131072

__device__ float g_y[(size_t)P_ * 64];
__device__ float g_z[(size_t)P_ * 64];

__device__ __forceinline__ uint32_t smem_u32(const void* p) {
    uint32_t a;
    asm("{ .reg .u64 t; cvta.to.shared.u64 t, %1; cvt.u32.u64 %0, t; }"
        : "=r"(a) : "l"(p));
    return a;
}
#define SWZ(x) ((x) ^ (((x) >> 3) & 0x70))

#define LDSM_X4(r, a) \
    asm volatile("ldmatrix.sync.aligned.m8n8.x4.shared.b16 {%0,%1,%2,%3}, [%4];" \
        : "=r"((r)[0]), "=r"((r)[1]), "=r"((r)[2]), "=r"((r)[3]) : "r"(a))
#define LDSM_X2(r, a) \
    asm volatile("ldmatrix.sync.aligned.m8n8.x2.shared.b16 {%0,%1}, [%2];" \
        : "=r"((r)[0]), "=r"((r)[1]) : "r"(a))
#define MMA_BF16(c, a, b) \
    asm volatile("mma.sync.aligned.m16n8k16.row.col.f32.bf16.bf16.f32 " \
        "{%0,%1,%2,%3}, {%4,%5,%6,%7}, {%8,%9}, {%0,%1,%2,%3};" \
        : "+f"((c)[0]), "+f"((c)[1]), "+f"((c)[2]), "+f"((c)[3]) \
        : "r"((a)[0]), "r"((a)[1]), "r"((a)[2]), "r"((a)[3]), \
          "r"((b)[0]), "r"((b)[1]))

// dynamic smem regions
#define SM_AH 0
#define SM_AL 16384
#define SM_BH 32768
#define SM_BL 49152
#define SM_TOTAL 65536

// ---------------------------------------------------------------------------
// k1: CTA tile 128 pts x 128 outs, K=64. 8 warps, warp = 16 pts x 128 outs.
// Wh/Wl built in-CTA from W. Single-nt mainloop with B double-buffering,
// 3 CTAs/SM for latency hiding.
// ---------------------------------------------------------------------------
__global__ __launch_bounds__(256, 3)
void k1_hmma(const float* __restrict__ x, const float* __restrict__ W)
{
    extern __shared__ char smem[];
    const uint32_t sb = smem_u32(smem);
    const int tid = threadIdx.x, wid = tid >> 5, lane = tid & 31;
    const size_t p0 = (size_t)blockIdx.x * 128;

    // --- stage B: build Wh/Wl from W, SW128-swizzled 128B rows, [o][d] ---
#pragma unroll
    for (int i = 0; i < 8; i++) {
        int idx = i * 256 + tid;            // element 0..2047: 4 bf16 each
        int o = idx >> 4, d4 = (idx & 15) * 4;
        unsigned long long hv = 0ull, lv = 0ull;
#pragma unroll
        for (int e = 0; e < 4; e++) {
            int d = d4 + e;
            float wc = (o < 64) ? W[o * 128 + d]
                                : W[(o - 64) * 128 + 64 + d] - W[(o - 64) * 128 + d];
            __nv_bfloat16 h = __float2bfloat16(wc);
            __nv_bfloat16 l = __float2bfloat16(wc - __bfloat162float(h));
            hv |= (unsigned long long)(*(unsigned short*)&h) << (16 * e);
            lv |= (unsigned long long)(*(unsigned short*)&l) << (16 * e);
        }
        uint32_t off = SWZ((uint32_t)(o * 128 + d4 * 2));
        *(unsigned long long*)(smem + SM_BH + off) = hv;
        *(unsigned long long*)(smem + SM_BL + off) = lv;
    }

    // --- stage A: x tile 128x64 f32 -> bf16 hi/lo, swizzled 8B stores ---
    const float4* xb = (const float4*)(x + p0 * 64);
#pragma unroll
    for (int i = 0; i < 8; i++) {
        int idx = i * 256 + tid;            // float4 units, 0..2047
        int row = idx >> 4, c4 = idx & 15;
        float4 v = __ldg(xb + idx);
        float f[4] = { v.x, v.y, v.z, v.w };
        unsigned long long hv = 0ull, lv = 0ull;
#pragma unroll
        for (int e = 0; e < 4; e++) {
            __nv_bfloat16 h = __float2bfloat16(f[e]);
            __nv_bfloat16 l = __float2bfloat16(f[e] - __bfloat162float(h));
            hv |= (unsigned long long)(*(unsigned short*)&h) << (16 * e);
            lv |= (unsigned long long)(*(unsigned short*)&l) << (16 * e);
        }
        uint32_t off = SWZ((uint32_t)(row * 128 + c4 * 8));
        *(unsigned long long*)(smem + SM_AH + off) = hv;
        *(unsigned long long*)(smem + SM_AL + off) = lv;
    }
    __syncthreads();

    // --- A fragments: rows wid*16..+15, 4 k-tiles ---
    uint32_t ah[4][4], al[4][4];
    {
        int r  = wid * 16 + (lane & 15);
        int cb = (lane >> 4) * 16;
#pragma unroll
        for (int kt = 0; kt < 4; kt++) {
            uint32_t off = SWZ((uint32_t)(r * 128 + kt * 32 + cb));
            LDSM_X4(ah[kt], sb + SM_AH + off);
            LDSM_X4(al[kt], sb + SM_AL + off);
        }
    }

    const int brow = lane & 7;
    const int bkb  = ((lane >> 3) & 1) * 16;

    // --- single-nt mainloop with B double buffer ---
    uint32_t bh[2][4][2], bl[2][4][2];
#pragma unroll
    for (int kt = 0; kt < 4; kt++) {
        uint32_t o0 = SWZ((uint32_t)(brow * 128 + kt * 32 + bkb));
        LDSM_X2(bh[0][kt], sb + SM_BH + o0);
        LDSM_X2(bl[0][kt], sb + SM_BL + o0);
    }

#pragma unroll
    for (int nt = 0; nt < 16; nt++) {
        const int cur = nt & 1, nxt = cur ^ 1;
        if (nt < 15) {
#pragma unroll
            for (int kt = 0; kt < 4; kt++) {
                uint32_t o1 = SWZ((uint32_t)(((nt + 1) * 8 + brow) * 128 + kt * 32 + bkb));
                LDSM_X2(bh[nxt][kt], sb + SM_BH + o1);
                LDSM_X2(bl[nxt][kt], sb + SM_BL + o1);
            }
        }
        float c[4] = {0.f, 0.f, 0.f, 0.f};
#pragma unroll
        for (int kt = 0; kt < 4; kt++) {
            MMA_BF16(c, ah[kt], bh[cur][kt]);
            MMA_BF16(c, ah[kt], bl[cur][kt]);
            MMA_BF16(c, al[kt], bh[cur][kt]);
        }
        size_t row = p0 + (size_t)wid * 16 + (lane >> 2);
        float* gb = (nt < 8) ? g_y : g_z;
        int col = (nt & 7) * 8 + (lane & 3) * 2;
        *(float2*)(gb + row * 64 + col)       = make_float2(c[0], c[1]);
        *(float2*)(gb + (row + 8) * 64 + col) = make_float2(c[2], c[3]);
    }
}

// ---------------------------------------------------------------------------
// Kernel 2: warp per point, lane owns dims (2*lane, 2*lane+1).
// ---------------------------------------------------------------------------
__global__ __launch_bounds__(256)
void k2_gather(const int*   __restrict__ ind,
               const float* __restrict__ gamma,
               const float* __restrict__ beta,
               float*       __restrict__ out)
{
    int warp = threadIdx.x >> 5, lane = threadIdx.x & 31;
    size_t p = (size_t)blockIdx.x * 8 + warp;
    size_t bbase = (p >> 13) << 13;

    const int*  ip    = ind + p * K_;
    const char* ybase = (const char*)(g_y + (bbase << 6)) + lane * 8;

    float m0 = -3.402823466e+38f, m1 = -3.402823466e+38f;
#pragma unroll
    for (int k = 0; k < K_; k++) {
        int j = __ldg(ip + k);
        float2 yv = *(const float2*)(ybase + ((size_t)j << 8));
        m0 = fmaxf(m0, yv.x);
        m1 = fmaxf(m1, yv.y);
    }

    float2 zv = *(const float2*)(g_z + (p << 6) + lane * 2);
    float h0 = m0 + zv.x, h1 = m1 + zv.y;

    float s  = h0 + h1;
    float ss = h0 * h0 + h1 * h1;
#pragma unroll
    for (int o2 = 16; o2; o2 >>= 1) {
        s  += __shfl_xor_sync(0xffffffffu, s, o2);
        ss += __shfl_xor_sync(0xffffffffu, ss, o2);
    }
    float mu  = s * (1.0f / 64.0f);
    float var = fmaxf(ss * (1.0f / 64.0f) - mu * mu, 0.0f);
    float rs  = rsqrtf(var + 1e-5f);

    float2 g  = *(const float2*)(gamma + lane * 2);
    float2 be = *(const float2*)(beta  + lane * 2);
    float hn0 = (h0 - mu) * rs * g.x + be.x;
    float hn1 = (h1 - mu) * rs * g.y + be.y;

    float r0 = 0.5f * hn0 * (1.0f + erff(hn0 * 0.7071067811865475f));
    float r1 = 0.5f * hn1 * (1.0f + erff(hn1 * 0.7071067811865475f));

    *(float2*)(out + (p << 6) + lane * 2) = make_float2(r0, r1);
}

// ---------------------------------------------------------------------------
extern "C" void kernel_launch(void* const* d_in, const int* in_sizes, int n_in,
                              void* d_out, int out_size)
{
    const float* x     = (const float*)d_in[0];
    const int*   ind   = (const int*)  d_in[1];
    const float* W     = (const float*)d_in[2];
    const float* gamma = (const float*)d_in[3];
    const float* beta  = (const float*)d_in[4];
    float*       out   = (float*)d_out;

    cudaFuncSetAttribute(k1_hmma, cudaFuncAttributeMaxDynamicSharedMemorySize, SM_TOTAL);

    k1_hmma <<<P_ / 128, 256, SM_TOTAL>>>(x, W);
    k2_gather<<<P_ / 8, 256>>>(ind, gamma, beta, out);
}